// round 5
// baseline (speedup 1.0000x reference)
#include <cuda_runtime.h>

// ---------------------------------------------------------------------------
// OpticalFlowLoss fused single-kernel for GB300 (sm_103a)
// pred, gt: [B=8, T=8, C=3, H=256, W=256] fp32 -> scalar fp32 loss
// ---------------------------------------------------------------------------

#define B_    8
#define T_    8
#define H_    256
#define W_    256
#define HW_   (H_ * W_)         // 65536
#define FRAME_STRIDE (3 * HW_)
#define NPAIRS (B_ * (T_ - 1))  // 56

#define TILE_W 64
#define TILE_H 32
#define HALO_W (TILE_W + 2)     // 66
#define HALO_H (TILE_H + 2)     // 34
#define SMEM_PITCH (HALO_W + 2) // 68

#define NBLOCKS ((W_ / TILE_W) * (H_ / TILE_H) * NPAIRS)  // 4*8*56 = 1792

#define EPSF 1e-3f
// mean element count: B*(T-1)*2*H*W = 8*7*2*65536
#define MEAN_COUNT 7340032.0

__device__ double g_accum;        // zero-initialized; self-resetting
__device__ unsigned int g_done;   // zero-initialized; self-resetting

__device__ __forceinline__ float gray3(float r, float g, float b) {
    return 0.2989f * r + 0.587f * g + 0.114f * b;
}

__device__ __forceinline__ float grayAt(const float* __restrict__ img, int base,
                                        int h, int w) {
    if ((unsigned)h >= H_ || (unsigned)w >= W_) return 0.0f;
    int off = base + h * W_ + w;
    float r = __ldg(img + off);
    float g = __ldg(img + off + HW_);
    float b = __ldg(img + off + 2 * HW_);
    return gray3(r, g, b);
}

__global__ __launch_bounds__(256, 8)
void flow_loss_kernel(const float* __restrict__ pred,
                      const float* __restrict__ gt,
                      float* __restrict__ out) {
    const int pair = blockIdx.z;          // 0..55
    const int b = pair / (T_ - 1);
    const int t = pair % (T_ - 1);

    const int tileX = blockIdx.x * TILE_W;
    const int tileY = blockIdx.y * TILE_H;

    const int base1 = (b * T_ + t) * FRAME_STRIDE;  // frame t
    const int base2 = base1 + FRAME_STRIDE;         // frame t+1

    __shared__ float sP[HALO_H][SMEM_PITCH];
    __shared__ float sG[HALO_H][SMEM_PITCH];

    for (int i = threadIdx.x; i < HALO_H * HALO_W; i += blockDim.x) {
        int hy = i / HALO_W;
        int hx = i - hy * HALO_W;
        int gh = tileY + hy - 1;
        int gw = tileX + hx - 1;
        sP[hy][hx] = grayAt(pred, base1, gh, gw);
        sG[hy][hx] = grayAt(gt,   base1, gh, gw);
    }
    __syncthreads();

    float acc = 0.0f;

    #pragma unroll
    for (int k = 0; k < (TILE_W * TILE_H) / 256; ++k) {
        int i  = threadIdx.x + k * 256;
        int ly = i / TILE_W;
        int lx = i - ly * TILE_W;
        int h  = tileY + ly;
        int w  = tileX + lx;
        int off = h * W_ + w;

        // ---- pred flow ----
        float p00 = sP[ly][lx],   p01 = sP[ly][lx + 1],   p02 = sP[ly][lx + 2];
        float p10 = sP[ly+1][lx],                          p12 = sP[ly+1][lx + 2];
        float p20 = sP[ly+2][lx], p21 = sP[ly+2][lx + 1], p22 = sP[ly+2][lx + 2];
        float pc  = sP[ly+1][lx+1];

        float IxP = (p00 - p02) + 2.0f * (p10 - p12) + (p20 - p22);
        float IyP = (p00 + 2.0f * p01 + p02) - (p20 + 2.0f * p21 + p22);

        float pr2 = __ldg(pred + base2 + off);
        float pg2 = __ldg(pred + base2 + off + HW_);
        float pb2 = __ldg(pred + base2 + off + 2 * HW_);
        float ItP = gray3(pr2, pg2, pb2) - pc;

        float invP = 1.0f / (IxP * IxP + IyP * IyP + EPSF);
        float uP = -IxP * ItP * invP;
        float vP = -IyP * ItP * invP;

        // ---- gt flow ----
        float g00 = sG[ly][lx],   g01 = sG[ly][lx + 1],   g02 = sG[ly][lx + 2];
        float g10 = sG[ly+1][lx],                          g12 = sG[ly+1][lx + 2];
        float g20 = sG[ly+2][lx], g21 = sG[ly+2][lx + 1], g22 = sG[ly+2][lx + 2];
        float gc  = sG[ly+1][lx+1];

        float IxG = (g00 - g02) + 2.0f * (g10 - g12) + (g20 - g22);
        float IyG = (g00 + 2.0f * g01 + g02) - (g20 + 2.0f * g21 + g22);

        float gr2 = __ldg(gt + base2 + off);
        float gg2 = __ldg(gt + base2 + off + HW_);
        float gb2 = __ldg(gt + base2 + off + 2 * HW_);
        float ItG = gray3(gr2, gg2, gb2) - gc;

        float invG = 1.0f / (IxG * IxG + IyG * IyG + EPSF);
        float uG = -IxG * ItG * invG;
        float vG = -IyG * ItG * invG;

        // ---- motion magnitude ----
        float gr1 = __ldg(gt + base1 + off);
        float gg1 = __ldg(gt + base1 + off + HW_);
        float gb1 = __ldg(gt + base1 + off + 2 * HW_);
        float mm = (fabsf(gr2 - gr1) + fabsf(gg2 - gg1) + fabsf(gb2 - gb1))
                   * (1.0f / 3.0f);

        acc += (fabsf(uP - uG) + fabsf(vP - vG)) * mm;
    }

    // --- block reduction ---
    #pragma unroll
    for (int s = 16; s > 0; s >>= 1)
        acc += __shfl_xor_sync(0xFFFFFFFFu, acc, s);

    __shared__ float warpSum[8];
    int lane = threadIdx.x & 31;
    int wid  = threadIdx.x >> 5;
    if (lane == 0) warpSum[wid] = acc;
    __syncthreads();

    if (wid == 0 && lane == 0) {
        float v = 0.0f;
        #pragma unroll
        for (int j = 0; j < 8; ++j) v += warpSum[j];
        atomicAdd(&g_accum, (double)v);
        __threadfence();
        unsigned ticket = atomicAdd(&g_done, 1u);
        if (ticket == NBLOCKS - 1) {
            // last CTA: finalize and self-reset for next graph replay
            out[0] = (float)(g_accum / MEAN_COUNT);
            g_accum = 0.0;
            __threadfence();
            g_done = 0u;
        }
    }
}

extern "C" void kernel_launch(void* const* d_in, const int* in_sizes, int n_in,
                              void* d_out, int out_size) {
    const float* pred = (const float*)d_in[0];
    const float* gt   = (const float*)d_in[1];
    float* out = (float*)d_out;

    dim3 grid(W_ / TILE_W, H_ / TILE_H, NPAIRS);  // (4, 8, 56) = 1792 CTAs
    flow_loss_kernel<<<grid, 256>>>(pred, gt, out);
}

// round 6
// speedup vs baseline: 1.2607x; 1.2607x over previous
#include <cuda_runtime.h>

// ---------------------------------------------------------------------------
// OpticalFlowLoss fused single-kernel, 4x vectorized (sm_103a)
// pred, gt: [B=8, T=8, C=3, H=256, W=256] fp32 -> scalar fp32 loss
// ---------------------------------------------------------------------------

#define B_    8
#define T_    8
#define H_    256
#define W_    256
#define HW_   (H_ * W_)          // 65536
#define FRAME_STRIDE (3 * HW_)
#define NPAIRS (B_ * (T_ - 1))   // 56

#define TILE_W 64
#define TILE_H 32
#define HALO_H (TILE_H + 2)      // 34
#define SCOLS  72                // covers global cols tileX-4 .. tileX+67
#define SLOTS  (SCOLS / 4)       // 18 float4 slots per halo row

#define NBLOCKS ((W_ / TILE_W) * (H_ / TILE_H) * NPAIRS)  // 4*8*56 = 1792

#define EPSF 1e-3f
#define MEAN_COUNT 7340032.0     // 8*7*2*256*256

__device__ double g_accum;       // zero-init; self-resetting
__device__ unsigned int g_done;  // zero-init; self-resetting

__device__ __forceinline__ float gray3(float r, float g, float b) {
    return 0.2989f * r + 0.587f * g + 0.114f * b;
}

// Compute flow (u,v) for 4 consecutive pixels from the gray halo tile in smem
// plus a vectorized read of frame t+1 RGB. Also returns the t+1 RGB float4s.
__device__ __forceinline__ void flow4(
    const float (*s)[SCOLS], int ly, int sx,
    const float* __restrict__ img, int off2,
    float4& r2, float4& g2, float4& b2,
    float* u, float* v)
{
    float4 a0 = *(const float4*)&s[ly    ][sx];
    float4 m0 = *(const float4*)&s[ly    ][sx + 4];
    float  c0 = s[ly    ][sx + 8];
    float4 a1 = *(const float4*)&s[ly + 1][sx];
    float4 m1 = *(const float4*)&s[ly + 1][sx + 4];
    float  c1 = s[ly + 1][sx + 8];
    float4 a2 = *(const float4*)&s[ly + 2][sx];
    float4 m2 = *(const float4*)&s[ly + 2][sx + 4];
    float  c2 = s[ly + 2][sx + 8];

    float t0[6] = {a0.w, m0.x, m0.y, m0.z, m0.w, c0};
    float t1[6] = {a1.w, m1.x, m1.y, m1.z, m1.w, c1};
    float t2[6] = {a2.w, m2.x, m2.y, m2.z, m2.w, c2};

    r2 = __ldg((const float4*)(img + off2));
    g2 = __ldg((const float4*)(img + off2 + HW_));
    b2 = __ldg((const float4*)(img + off2 + 2 * HW_));

    float gy2[4] = {gray3(r2.x, g2.x, b2.x), gray3(r2.y, g2.y, b2.y),
                    gray3(r2.z, g2.z, b2.z), gray3(r2.w, g2.w, b2.w)};

    #pragma unroll
    for (int p = 0; p < 4; ++p) {
        float Ix = (t0[p] - t0[p + 2]) + 2.0f * (t1[p] - t1[p + 2])
                 + (t2[p] - t2[p + 2]);
        float Iy = (t0[p] + 2.0f * t0[p + 1] + t0[p + 2])
                 - (t2[p] + 2.0f * t2[p + 1] + t2[p + 2]);
        float It = gy2[p] - t1[p + 1];
        float inv = __fdividef(1.0f, Ix * Ix + Iy * Iy + EPSF);
        u[p] = -Ix * It * inv;
        v[p] = -Iy * It * inv;
    }
}

__global__ __launch_bounds__(256)
void flow_loss_kernel(const float* __restrict__ pred,
                      const float* __restrict__ gt,
                      float* __restrict__ out) {
    const int pair = blockIdx.z;          // 0..55
    const int b = pair / (T_ - 1);
    const int t = pair % (T_ - 1);

    const int tileX = blockIdx.x * TILE_W;
    const int tileY = blockIdx.y * TILE_H;

    const int base1 = (b * T_ + t) * FRAME_STRIDE;  // frame t
    const int base2 = base1 + FRAME_STRIDE;         // frame t+1

    __shared__ float sP[HALO_H][SCOLS];
    __shared__ float sG[HALO_H][SCOLS];

    // --- vectorized halo fill: gray of frame t for pred and gt ---
    for (int i = threadIdx.x; i < HALO_H * SLOTS; i += 256) {
        int hy = i / SLOTS;
        int sl = i - hy * SLOTS;
        int gh = tileY + hy - 1;
        int gc = tileX - 4 + sl * 4;
        float4 vp = make_float4(0.f, 0.f, 0.f, 0.f);
        float4 vg = vp;
        if ((unsigned)gh < H_ && (unsigned)gc < W_) {
            int off = base1 + gh * W_ + gc;
            float4 r = __ldg((const float4*)(pred + off));
            float4 g = __ldg((const float4*)(pred + off + HW_));
            float4 bb = __ldg((const float4*)(pred + off + 2 * HW_));
            vp = make_float4(gray3(r.x, g.x, bb.x), gray3(r.y, g.y, bb.y),
                             gray3(r.z, g.z, bb.z), gray3(r.w, g.w, bb.w));
            r  = __ldg((const float4*)(gt + off));
            g  = __ldg((const float4*)(gt + off + HW_));
            bb = __ldg((const float4*)(gt + off + 2 * HW_));
            vg = make_float4(gray3(r.x, g.x, bb.x), gray3(r.y, g.y, bb.y),
                             gray3(r.z, g.z, bb.z), gray3(r.w, g.w, bb.w));
        }
        *(float4*)&sP[hy][sl * 4] = vp;
        *(float4*)&sG[hy][sl * 4] = vg;
    }
    __syncthreads();

    float acc = 0.0f;

    #pragma unroll
    for (int k = 0; k < 2; ++k) {
        int i  = threadIdx.x + k * 256;
        int ly = i >> 4;            // 0..31
        int sx = (i & 15) * 4;      // 0..60, tile-local col of first pixel
        int h  = tileY + ly;
        int w0 = tileX + sx;
        int off = h * W_ + w0;

        float uP[4], vP[4], uG[4], vG[4];
        float4 pr2, pg2, pb2, gr2, gg2, gb2;

        flow4(sP, ly, sx, pred, base2 + off, pr2, pg2, pb2, uP, vP);
        flow4(sG, ly, sx, gt,   base2 + off, gr2, gg2, gb2, uG, vG);

        float4 gr1 = __ldg((const float4*)(gt + base1 + off));
        float4 gg1 = __ldg((const float4*)(gt + base1 + off + HW_));
        float4 gb1 = __ldg((const float4*)(gt + base1 + off + 2 * HW_));

        float mm0 = (fabsf(gr2.x - gr1.x) + fabsf(gg2.x - gg1.x) + fabsf(gb2.x - gb1.x)) * (1.f/3.f);
        float mm1 = (fabsf(gr2.y - gr1.y) + fabsf(gg2.y - gg1.y) + fabsf(gb2.y - gb1.y)) * (1.f/3.f);
        float mm2 = (fabsf(gr2.z - gr1.z) + fabsf(gg2.z - gg1.z) + fabsf(gb2.z - gb1.z)) * (1.f/3.f);
        float mm3 = (fabsf(gr2.w - gr1.w) + fabsf(gg2.w - gg1.w) + fabsf(gb2.w - gb1.w)) * (1.f/3.f);

        acc += (fabsf(uP[0] - uG[0]) + fabsf(vP[0] - vG[0])) * mm0;
        acc += (fabsf(uP[1] - uG[1]) + fabsf(vP[1] - vG[1])) * mm1;
        acc += (fabsf(uP[2] - uG[2]) + fabsf(vP[2] - vG[2])) * mm2;
        acc += (fabsf(uP[3] - uG[3]) + fabsf(vP[3] - vG[3])) * mm3;
    }

    // --- block reduction ---
    #pragma unroll
    for (int s = 16; s > 0; s >>= 1)
        acc += __shfl_xor_sync(0xFFFFFFFFu, acc, s);

    __shared__ float warpSum[8];
    int lane = threadIdx.x & 31;
    int wid  = threadIdx.x >> 5;
    if (lane == 0) warpSum[wid] = acc;
    __syncthreads();

    if (wid == 0 && lane == 0) {
        float v = 0.0f;
        #pragma unroll
        for (int j = 0; j < 8; ++j) v += warpSum[j];
        atomicAdd(&g_accum, (double)v);
        __threadfence();
        unsigned ticket = atomicAdd(&g_done, 1u);
        if (ticket == NBLOCKS - 1) {
            out[0] = (float)(g_accum / MEAN_COUNT);
            g_accum = 0.0;
            __threadfence();
            g_done = 0u;
        }
    }
}

extern "C" void kernel_launch(void* const* d_in, const int* in_sizes, int n_in,
                              void* d_out, int out_size) {
    const float* pred = (const float*)d_in[0];
    const float* gt   = (const float*)d_in[1];
    float* out = (float*)d_out;

    dim3 grid(W_ / TILE_W, H_ / TILE_H, NPAIRS);  // (4, 8, 56) = 1792 CTAs
    flow_loss_kernel<<<grid, 256>>>(pred, gt, out);
}